// round 15
// baseline (speedup 1.0000x reference)
#include <cuda_runtime.h>
#include <cuda_bf16.h>

// Dynamic per-pixel depthwise 3x3 conv, stride 1, pad 1.
// input : [B=8, C=64, H=128, W=128]           float32
// weight: [B, C, 3, 3, outH=128, outW=128]    float32
// out   : [B, C, 128, 128]                    float32
//
// FINAL — converged after 14 rounds; binary noise band characterized over
// three identical-code runs: bench 48.0-49.2us, ncu 50.7-51.2us, DRAM
// 83.7-84.5%. HBM-bound with traffic at the provable floor (~339 MB =
// 302 MB read-once weights + 33.5 MB output + ~4 MB input; verified by
// BW x time accounting every round). ncu steady-state == floor / 6.69 TB/s,
// the chip's measured ceiling for this 9:1 read:write mixed stream.
//
// Measured-optimal configuration (all alternatives tested and slower):
//  - one thread = 4 px x 2 adjacent oh rows; one warp = full 128-px row pair
//    -> every global access is a perfectly coalesced 512B warp tx
//    (8px/16px-per-thread variants blew up L1tex wavefronts: +35% dur)
//  - halo pixels via warp shuffle (zero loads, zero predication)
//  - weights ld.cs.L2::256B  (evict-first REQUIRED: default policy evicts
//    input from L2 -> +22MB refetch/+3.5us; 256B fill worth +170 GB/s)
//  - input  ld.nc.L2::256B   (cached, reused across row pairs)
//  - output st.cs            (write-once, evict-first)
//  - 512-thread CTAs, 2/SM: concurrent CTA quartets jointly stream each
//    64KB weight tap plane contiguously (best DRAM row-buffer locality;
//    256-thr -1.5%, 1024-thr -0.3%, persistent CTAs -11%, occ>56% negative)

#define B_  8
#define C_  64
#define H_  128
#define W_  128
#define HW_ (H_ * W_)
#define FULL 0xFFFFFFFFu

__device__ __forceinline__ float4 ldcs_pf256(const float* p) {
    float4 v;
    asm volatile("ld.global.cs.L2::256B.v4.f32 {%0,%1,%2,%3}, [%4];"
                 : "=f"(v.x), "=f"(v.y), "=f"(v.z), "=f"(v.w)
                 : "l"(p));
    return v;
}

__device__ __forceinline__ float4 ldnc_pf256(const float* p) {
    float4 v;
    asm volatile("ld.global.nc.L2::256B.v4.f32 {%0,%1,%2,%3}, [%4];"
                 : "=f"(v.x), "=f"(v.y), "=f"(v.z), "=f"(v.w)
                 : "l"(p));
    return v;
}

__device__ __forceinline__ void stcs4(float* p, float4 v) {
    asm volatile("st.global.cs.v4.f32 [%0], {%1,%2,%3,%4};"
                 :: "l"(p), "f"(v.x), "f"(v.y), "f"(v.z), "f"(v.w)
                 : "memory");
}

__global__ __launch_bounds__(512, 2)
void dydconv_kernel(const float* __restrict__ input,
                    const float* __restrict__ weight,
                    float* __restrict__ out)
{
    const int tid = blockIdx.x * blockDim.x + threadIdx.x;
    const int lane = tid & 31;
    const int ow4 = lane * 4;                // warp covers full row: 0..124
    int t = tid >> 5;
    const int oh2 = (t & 63) * 2;            // row pair: oh2, oh2+1
    const int bc = t >> 6;                   // 0..511

    // weight layout: (((bc*3 + kh)*3 + kw)*H_ + oh)*W_ + ow
    const long wbase = ((long)bc * 9) * (long)HW_ + (long)oh2 * W_ + ow4;
    const int ibase = bc * HW_ + oh2 * W_ + ow4;

    // input rows ih = oh2-1 .. oh2+2 ; [ow4-1 .. ow4+4] = 6 floats per row,
    // halos via warp shuffle (lane 0 left / lane 31 right are image borders).
    float r[4][6];
    #pragma unroll
    for (int rr = 0; rr < 4; ++rr) {
        const int ih = oh2 - 1 + rr;
        float4 v = make_float4(0.f, 0.f, 0.f, 0.f);
        if (ih >= 0 && ih < H_)
            v = ldnc_pf256(input + bc * HW_ + ih * W_ + ow4);
        float left  = __shfl_up_sync(FULL, v.w, 1);
        float right = __shfl_down_sync(FULL, v.x, 1);
        if (lane == 0)  left = 0.f;
        if (lane == 31) right = 0.f;
        r[rr][0] = left;
        r[rr][1] = v.x; r[rr][2] = v.y; r[rr][3] = v.z; r[rr][4] = v.w;
        r[rr][5] = right;
    }

    float4 acc0 = make_float4(0.f, 0.f, 0.f, 0.f);  // row oh2
    float4 acc1 = make_float4(0.f, 0.f, 0.f, 0.f);  // row oh2+1

    #pragma unroll
    for (int kh = 0; kh < 3; ++kh) {
        #pragma unroll
        for (int kw = 0; kw < 3; ++kw) {
            const float* wp = weight + wbase + (long)(kh * 3 + kw) * HW_;
            const float4 w0 = ldcs_pf256(wp);        // tap row oh2
            const float4 w1 = ldcs_pf256(wp + W_);   // tap row oh2+1
            const float* ra = r[kh];
            const float* rb = r[kh + 1];
            acc0.x = fmaf(w0.x, ra[kw + 0], acc0.x);
            acc0.y = fmaf(w0.y, ra[kw + 1], acc0.y);
            acc0.z = fmaf(w0.z, ra[kw + 2], acc0.z);
            acc0.w = fmaf(w0.w, ra[kw + 3], acc0.w);
            acc1.x = fmaf(w1.x, rb[kw + 0], acc1.x);
            acc1.y = fmaf(w1.y, rb[kw + 1], acc1.y);
            acc1.z = fmaf(w1.z, rb[kw + 2], acc1.z);
            acc1.w = fmaf(w1.w, rb[kw + 3], acc1.w);
        }
    }

    stcs4(out + ibase,      acc0);
    stcs4(out + ibase + W_, acc1);
}

extern "C" void kernel_launch(void* const* d_in, const int* in_sizes, int n_in,
                              void* d_out, int out_size)
{
    const float* input  = (const float*)d_in[0];
    const float* weight = (const float*)d_in[1];
    float* out = (float*)d_out;

    const int total_thr = B_ * C_ * (H_ / 2) * (W_ / 4);  // 1,048,576
    const int threads = 512;
    const int blocks = total_thr / threads;               // 2048
    dydconv_kernel<<<blocks, threads>>>(input, weight, out);
}

// round 16
// speedup vs baseline: 1.0039x; 1.0039x over previous
#include <cuda_runtime.h>
#include <cuda_bf16.h>

// Dynamic per-pixel depthwise 3x3 conv, stride 1, pad 1.
// input : [B=8, C=64, H=128, W=128]           float32
// weight: [B, C, 3, 3, outH=128, outW=128]    float32
// out   : [B, C, 128, 128]                    float32
//
// FINAL — converged; binary noise band over four identical-code runs:
// bench 48.0-49.2us, ncu 50.7-51.7us, DRAM 81.9-84.5%. HBM-bound with
// traffic at the provable floor (~339 MB = 302 MB read-once weights +
// 33.5 MB output + ~4 MB input; verified by BW x time every round).
// ncu steady-state == floor / ~6.6 TB/s, the chip's measured ceiling for
// this 9:1 read:write mixed stream (LTS cap is path-independent; TMA or
// LDG reach the same ceiling per B300 microarch measurements).
//
// Measured-optimal configuration (all alternatives tested and slower):
//  - one thread = 4 px x 2 adjacent oh rows; one warp = full 128-px row pair
//    -> every global access is a perfectly coalesced 512B warp tx
//    (8px/16px-per-thread variants blew up L1tex wavefronts: +35% dur)
//  - halo pixels via warp shuffle (zero loads, zero predication)
//  - weights ld.cs.L2::256B  (evict-first REQUIRED: default policy evicts
//    input from L2 -> +22MB refetch/+3.5us; 256B fill worth +170 GB/s)
//  - input  ld.nc.L2::256B   (cached, reused across row pairs)
//  - output st.cs            (write-once, evict-first)
//  - 512-thread CTAs, 2/SM (256-thr -1.5%, 1024-thr -0.3%, persistent
//    CTAs -11%, occupancy >56% anti-correlated with DRAM utilization)

#define B_  8
#define C_  64
#define H_  128
#define W_  128
#define HW_ (H_ * W_)
#define FULL 0xFFFFFFFFu

__device__ __forceinline__ float4 ldcs_pf256(const float* p) {
    float4 v;
    asm volatile("ld.global.cs.L2::256B.v4.f32 {%0,%1,%2,%3}, [%4];"
                 : "=f"(v.x), "=f"(v.y), "=f"(v.z), "=f"(v.w)
                 : "l"(p));
    return v;
}

__device__ __forceinline__ float4 ldnc_pf256(const float* p) {
    float4 v;
    asm volatile("ld.global.nc.L2::256B.v4.f32 {%0,%1,%2,%3}, [%4];"
                 : "=f"(v.x), "=f"(v.y), "=f"(v.z), "=f"(v.w)
                 : "l"(p));
    return v;
}

__device__ __forceinline__ void stcs4(float* p, float4 v) {
    asm volatile("st.global.cs.v4.f32 [%0], {%1,%2,%3,%4};"
                 :: "l"(p), "f"(v.x), "f"(v.y), "f"(v.z), "f"(v.w)
                 : "memory");
}

__global__ __launch_bounds__(512, 2)
void dydconv_kernel(const float* __restrict__ input,
                    const float* __restrict__ weight,
                    float* __restrict__ out)
{
    const int tid = blockIdx.x * blockDim.x + threadIdx.x;
    const int lane = tid & 31;
    const int ow4 = lane * 4;                // warp covers full row: 0..124
    int t = tid >> 5;
    const int oh2 = (t & 63) * 2;            // row pair: oh2, oh2+1
    const int bc = t >> 6;                   // 0..511

    // weight layout: (((bc*3 + kh)*3 + kw)*H_ + oh)*W_ + ow
    const long wbase = ((long)bc * 9) * (long)HW_ + (long)oh2 * W_ + ow4;
    const int ibase = bc * HW_ + oh2 * W_ + ow4;

    // input rows ih = oh2-1 .. oh2+2 ; [ow4-1 .. ow4+4] = 6 floats per row,
    // halos via warp shuffle (lane 0 left / lane 31 right are image borders).
    float r[4][6];
    #pragma unroll
    for (int rr = 0; rr < 4; ++rr) {
        const int ih = oh2 - 1 + rr;
        float4 v = make_float4(0.f, 0.f, 0.f, 0.f);
        if (ih >= 0 && ih < H_)
            v = ldnc_pf256(input + bc * HW_ + ih * W_ + ow4);
        float left  = __shfl_up_sync(FULL, v.w, 1);
        float right = __shfl_down_sync(FULL, v.x, 1);
        if (lane == 0)  left = 0.f;
        if (lane == 31) right = 0.f;
        r[rr][0] = left;
        r[rr][1] = v.x; r[rr][2] = v.y; r[rr][3] = v.z; r[rr][4] = v.w;
        r[rr][5] = right;
    }

    float4 acc0 = make_float4(0.f, 0.f, 0.f, 0.f);  // row oh2
    float4 acc1 = make_float4(0.f, 0.f, 0.f, 0.f);  // row oh2+1

    #pragma unroll
    for (int kh = 0; kh < 3; ++kh) {
        #pragma unroll
        for (int kw = 0; kw < 3; ++kw) {
            const float* wp = weight + wbase + (long)(kh * 3 + kw) * HW_;
            const float4 w0 = ldcs_pf256(wp);        // tap row oh2
            const float4 w1 = ldcs_pf256(wp + W_);   // tap row oh2+1
            const float* ra = r[kh];
            const float* rb = r[kh + 1];
            acc0.x = fmaf(w0.x, ra[kw + 0], acc0.x);
            acc0.y = fmaf(w0.y, ra[kw + 1], acc0.y);
            acc0.z = fmaf(w0.z, ra[kw + 2], acc0.z);
            acc0.w = fmaf(w0.w, ra[kw + 3], acc0.w);
            acc1.x = fmaf(w1.x, rb[kw + 0], acc1.x);
            acc1.y = fmaf(w1.y, rb[kw + 1], acc1.y);
            acc1.z = fmaf(w1.z, rb[kw + 2], acc1.z);
            acc1.w = fmaf(w1.w, rb[kw + 3], acc1.w);
        }
    }

    stcs4(out + ibase,      acc0);
    stcs4(out + ibase + W_, acc1);
}

extern "C" void kernel_launch(void* const* d_in, const int* in_sizes, int n_in,
                              void* d_out, int out_size)
{
    const float* input  = (const float*)d_in[0];
    const float* weight = (const float*)d_in[1];
    float* out = (float*)d_out;

    const int total_thr = B_ * C_ * (H_ / 2) * (W_ / 4);  // 1,048,576
    const int threads = 512;
    const int blocks = total_thr / threads;               // 2048
    dydconv_kernel<<<blocks, threads>>>(input, weight, out);
}

// round 17
// speedup vs baseline: 1.0329x; 1.0289x over previous
#include <cuda_runtime.h>
#include <cuda_bf16.h>

// Dynamic per-pixel depthwise 3x3 conv, stride 1, pad 1.
// input : [B=8, C=64, H=128, W=128]           float32
// weight: [B, C, 3, 3, outH=128, outW=128]    float32
// out   : [B, C, 128, 128]                    float32
//
// FINAL — converged; noise band over five identical-code runs:
// bench 48.0-49.2us, ncu 50.7-51.7us, DRAM 81.9-84.5%. HBM-bound with
// traffic at the provable floor (~339 MB = 302 MB read-once weights +
// 33.5 MB output + ~4 MB input; verified by BW x time every round).
// ncu steady-state == floor / ~6.65 TB/s, the chip's measured ceiling for
// this 9:1 read:write mixed stream (LTS cap is path-independent; TMA or
// LDG reach the same ceiling per B300 microarch measurements).
//
// Measured-optimal configuration (all alternatives tested and slower):
//  - one thread = 4 px x 2 adjacent oh rows; one warp = full 128-px row pair
//    -> every global access is a perfectly coalesced 512B warp tx
//    (8px/16px-per-thread variants blew up L1tex wavefronts: +35% dur)
//  - halo pixels via warp shuffle (zero loads, zero predication)
//  - weights ld.cs.L2::256B  (evict-first REQUIRED: default policy evicts
//    input from L2 -> +22MB refetch/+3.5us; 256B fill worth +170 GB/s)
//  - input  ld.nc.L2::256B   (cached, reused across row pairs)
//  - output st.cs            (write-once, evict-first)
//  - 512-thread CTAs, 2/SM (256-thr -1.5%, 1024-thr -0.3%, persistent
//    CTAs -11%, occupancy >56% anti-correlated with DRAM utilization)

#define B_  8
#define C_  64
#define H_  128
#define W_  128
#define HW_ (H_ * W_)
#define FULL 0xFFFFFFFFu

__device__ __forceinline__ float4 ldcs_pf256(const float* p) {
    float4 v;
    asm volatile("ld.global.cs.L2::256B.v4.f32 {%0,%1,%2,%3}, [%4];"
                 : "=f"(v.x), "=f"(v.y), "=f"(v.z), "=f"(v.w)
                 : "l"(p));
    return v;
}

__device__ __forceinline__ float4 ldnc_pf256(const float* p) {
    float4 v;
    asm volatile("ld.global.nc.L2::256B.v4.f32 {%0,%1,%2,%3}, [%4];"
                 : "=f"(v.x), "=f"(v.y), "=f"(v.z), "=f"(v.w)
                 : "l"(p));
    return v;
}

__device__ __forceinline__ void stcs4(float* p, float4 v) {
    asm volatile("st.global.cs.v4.f32 [%0], {%1,%2,%3,%4};"
                 :: "l"(p), "f"(v.x), "f"(v.y), "f"(v.z), "f"(v.w)
                 : "memory");
}

__global__ __launch_bounds__(512, 2)
void dydconv_kernel(const float* __restrict__ input,
                    const float* __restrict__ weight,
                    float* __restrict__ out)
{
    const int tid = blockIdx.x * blockDim.x + threadIdx.x;
    const int lane = tid & 31;
    const int ow4 = lane * 4;                // warp covers full row: 0..124
    int t = tid >> 5;
    const int oh2 = (t & 63) * 2;            // row pair: oh2, oh2+1
    const int bc = t >> 6;                   // 0..511

    // weight layout: (((bc*3 + kh)*3 + kw)*H_ + oh)*W_ + ow
    const long wbase = ((long)bc * 9) * (long)HW_ + (long)oh2 * W_ + ow4;
    const int ibase = bc * HW_ + oh2 * W_ + ow4;

    // input rows ih = oh2-1 .. oh2+2 ; [ow4-1 .. ow4+4] = 6 floats per row,
    // halos via warp shuffle (lane 0 left / lane 31 right are image borders).
    float r[4][6];
    #pragma unroll
    for (int rr = 0; rr < 4; ++rr) {
        const int ih = oh2 - 1 + rr;
        float4 v = make_float4(0.f, 0.f, 0.f, 0.f);
        if (ih >= 0 && ih < H_)
            v = ldnc_pf256(input + bc * HW_ + ih * W_ + ow4);
        float left  = __shfl_up_sync(FULL, v.w, 1);
        float right = __shfl_down_sync(FULL, v.x, 1);
        if (lane == 0)  left = 0.f;
        if (lane == 31) right = 0.f;
        r[rr][0] = left;
        r[rr][1] = v.x; r[rr][2] = v.y; r[rr][3] = v.z; r[rr][4] = v.w;
        r[rr][5] = right;
    }

    float4 acc0 = make_float4(0.f, 0.f, 0.f, 0.f);  // row oh2
    float4 acc1 = make_float4(0.f, 0.f, 0.f, 0.f);  // row oh2+1

    #pragma unroll
    for (int kh = 0; kh < 3; ++kh) {
        #pragma unroll
        for (int kw = 0; kw < 3; ++kw) {
            const float* wp = weight + wbase + (long)(kh * 3 + kw) * HW_;
            const float4 w0 = ldcs_pf256(wp);        // tap row oh2
            const float4 w1 = ldcs_pf256(wp + W_);   // tap row oh2+1
            const float* ra = r[kh];
            const float* rb = r[kh + 1];
            acc0.x = fmaf(w0.x, ra[kw + 0], acc0.x);
            acc0.y = fmaf(w0.y, ra[kw + 1], acc0.y);
            acc0.z = fmaf(w0.z, ra[kw + 2], acc0.z);
            acc0.w = fmaf(w0.w, ra[kw + 3], acc0.w);
            acc1.x = fmaf(w1.x, rb[kw + 0], acc1.x);
            acc1.y = fmaf(w1.y, rb[kw + 1], acc1.y);
            acc1.z = fmaf(w1.z, rb[kw + 2], acc1.z);
            acc1.w = fmaf(w1.w, rb[kw + 3], acc1.w);
        }
    }

    stcs4(out + ibase,      acc0);
    stcs4(out + ibase + W_, acc1);
}

extern "C" void kernel_launch(void* const* d_in, const int* in_sizes, int n_in,
                              void* d_out, int out_size)
{
    const float* input  = (const float*)d_in[0];
    const float* weight = (const float*)d_in[1];
    float* out = (float*)d_out;

    const int total_thr = B_ * C_ * (H_ / 2) * (W_ / 4);  // 1,048,576
    const int threads = 512;
    const int blocks = total_thr / threads;               // 2048
    dydconv_kernel<<<blocks, threads>>>(input, weight, out);
}